// round 2
// baseline (speedup 1.0000x reference)
#include <cuda_runtime.h>
#include <cuda_bf16.h>

// Bicubic x4 upsample, Keys a=-0.5, matching jax.image.resize(method="cubic").
// Input:  (16,3,256,256) fp32  -> 48 planes of 256x256
// Output: (16,3,1024,1024) fp32 -> 48 planes of 1024x1024
//
// One thread produces one 4x4 output cell from a 5x5 input neighborhood.
// Interior cells use compile-time-constant phase weights (exact, sum==1).
// Border cells renormalize over in-range taps, matching jax's weight matrix.

#define IN_W   256
#define IN_H   256
#define OUT_W  1024
#define PLANE_IN  (IN_W * IN_H)          // 65536
#define PLANE_OUT (OUT_W * OUT_W)        // 1048576

// Keys(a=-0.5) weights for the 4 phases, laid out on tap offsets -2..+2
// relative to the cell base q. Phases 0,1 use taps -2..+1; phases 2,3 use -1..+2.
// All values are exact binary fractions; each row sums to exactly 1.0f.
#define A0 (-0.0439453125f)
#define A1 ( 0.3896484375f)
#define A2 ( 0.7275390625f)
#define A3 (-0.0732421875f)
#define B0 (-0.0068359375f)
#define B1 ( 0.0908203125f)
#define B2 ( 0.9638671875f)
#define B3 (-0.0478515625f)

__device__ __forceinline__ void make_border_weights(int q, float w[4][5]) {
    const float tbl[4][5] = {
        {A0,  A1,  A2,  A3,  0.f},
        {B0,  B1,  B2,  B3,  0.f},
        {0.f, B3,  B2,  B1,  B0 },
        {0.f, A3,  A2,  A1,  A0 }
    };
#pragma unroll
    for (int p = 0; p < 4; p++) {
        float s = 0.f;
#pragma unroll
        for (int j = 0; j < 5; j++) {
            int idx = q - 2 + j;
            float ww = (idx >= 0 && idx < IN_W) ? tbl[p][j] : 0.f;
            w[p][j] = ww;
            s += ww;
        }
        float inv = 1.0f / s;   // jax normalizes weights to sum 1 over valid taps
#pragma unroll
        for (int j = 0; j < 5; j++) w[p][j] *= inv;
    }
}

__global__ void __launch_bounds__(256)
bicubic4x_kernel(const float* __restrict__ in, float* __restrict__ out)
{
    int id = blockIdx.x * 256 + threadIdx.x;   // 48*256*256 threads total
    int qx    = id & 255;
    int qy    = (id >> 8) & 255;
    int plane = id >> 16;

    const float* ip = in  + (size_t)plane * PLANE_IN;
    float*       op = out + (size_t)plane * PLANE_OUT
                          + (size_t)(qy * 4) * OUT_W + (size_t)(qx * 4);

    float acc[4][4];
#pragma unroll
    for (int i = 0; i < 4; i++)
#pragma unroll
        for (int j = 0; j < 4; j++) acc[i][j] = 0.f;

    bool interior = (qx >= 2) & (qx <= IN_W - 3) & (qy >= 2) & (qy <= IN_H - 3);

    if (interior) {
        // --- fast path: literal weights -> FFMA-imm, unclamped coalesced loads ---
        const float* base = ip + (qy - 2) * IN_W + (qx - 2);
#pragma unroll
        for (int r = 0; r < 5; r++) {
            const float* row = base + r * IN_W;
            float v0 = __ldg(row + 0);
            float v1 = __ldg(row + 1);
            float v2 = __ldg(row + 2);
            float v3 = __ldg(row + 3);
            float v4 = __ldg(row + 4);

            float h[4];
            h[0] = fmaf(A0, v0, fmaf(A1, v1, fmaf(A2, v2, A3 * v3)));
            h[1] = fmaf(B0, v0, fmaf(B1, v1, fmaf(B2, v2, B3 * v3)));
            h[2] = fmaf(B3, v1, fmaf(B2, v2, fmaf(B1, v3, B0 * v4)));
            h[3] = fmaf(A3, v1, fmaf(A2, v2, fmaf(A1, v3, A0 * v4)));

            // vertical weights per (phase py, row r); structural zeros skipped
            const float wy[4][5] = {
                {A0,  A1,  A2,  A3,  0.f},
                {B0,  B1,  B2,  B3,  0.f},
                {0.f, B3,  B2,  B1,  B0 },
                {0.f, A3,  A2,  A1,  A0 }
            };
#pragma unroll
            for (int py = 0; py < 4; py++) {
                float w = wy[py][r];     // compile-time constant after unroll
#pragma unroll
                for (int px = 0; px < 4; px++)
                    acc[py][px] = fmaf(w, h[px], acc[py][px]);
            }
        }
    } else {
        // --- border path: masked taps + renormalization (matches jax exactly) ---
        float wx[4][5], wy[4][5];
        make_border_weights(qx, wx);
        make_border_weights(qy, wy);
#pragma unroll
        for (int r = 0; r < 5; r++) {
            int ry = qy - 2 + r;
            ry = ry < 0 ? 0 : (ry > IN_H - 1 ? IN_H - 1 : ry);   // weight is 0 there anyway
            const float* row = ip + ry * IN_W;
            float v[5];
#pragma unroll
            for (int j = 0; j < 5; j++) {
                int cx = qx - 2 + j;
                cx = cx < 0 ? 0 : (cx > IN_W - 1 ? IN_W - 1 : cx);
                v[j] = __ldg(row + cx);
            }
            float h[4];
#pragma unroll
            for (int p = 0; p < 4; p++) {
                float s = wx[p][0] * v[0];
#pragma unroll
                for (int j = 1; j < 5; j++) s = fmaf(wx[p][j], v[j], s);
                h[p] = s;
            }
#pragma unroll
            for (int py = 0; py < 4; py++) {
                float w = wy[py][r];
#pragma unroll
                for (int px = 0; px < 4; px++)
                    acc[py][px] = fmaf(w, h[px], acc[py][px]);
            }
        }
    }

    // 4 rows x float4 stores, 16B-aligned, coalesced across the warp
#pragma unroll
    for (int py = 0; py < 4; py++) {
        float4 o = make_float4(acc[py][0], acc[py][1], acc[py][2], acc[py][3]);
        *reinterpret_cast<float4*>(op + (size_t)py * OUT_W) = o;
    }
}

extern "C" void kernel_launch(void* const* d_in, const int* in_sizes, int n_in,
                              void* d_out, int out_size)
{
    const float* x   = (const float*)d_in[0];
    float*       out = (float*)d_out;

    // 48 planes * 256 * 256 cells, one thread per 4x4 output cell
    const int total_threads = 48 * 256 * 256;     // 3,145,728
    const int block = 256;
    const int grid  = total_threads / block;      // 12288

    bicubic4x_kernel<<<grid, block>>>(x, out);
}

// round 3
// speedup vs baseline: 1.7145x; 1.7145x over previous
#include <cuda_runtime.h>
#include <cuda_bf16.h>

// Bicubic x4 upsample, Keys a=-0.5, matching jax.image.resize(method="cubic").
// Separable two-pass with shared memory:
//   input (16,3,256,256) f32 -> output (16,3,1024,1024) f32
// Block = 256 threads, handles 32x32 input cells -> 128x128 output tile.
//   Phase A: stage 36x36 input halo in smem
//   Phase B: horizontal 4-tap pass -> sh[36][128] (each halo row filtered ONCE)
//   Phase C: vertical 4-tap pass, float4 stores
// Borders use masked+renormalized weights (exact jax semantics).

#define IN_W   256
#define IN_H   256
#define OUT_W  1024
#define PLANE_IN  (IN_W * IN_H)
#define PLANE_OUT (OUT_W * OUT_W)

// Keys(a=-0.5) phase weights on tap offsets -2..+2 (exact binary fractions,
// each interior row sums to exactly 1.0f).
#define A0 (-0.0439453125f)
#define A1 ( 0.3896484375f)
#define A2 ( 0.7275390625f)
#define A3 (-0.0732421875f)
#define B0 (-0.0068359375f)
#define B1 ( 0.0908203125f)
#define B2 ( 0.9638671875f)
#define B3 (-0.0478515625f)

// Border weights for a single cell q: mask out-of-range taps, renormalize.
__device__ __forceinline__ void border_weights(int q, float w[4][5]) {
    const float tbl[4][5] = {
        {A0,  A1,  A2,  A3,  0.f},
        {B0,  B1,  B2,  B3,  0.f},
        {0.f, B3,  B2,  B1,  B0 },
        {0.f, A3,  A2,  A1,  A0 }
    };
#pragma unroll
    for (int p = 0; p < 4; p++) {
        float s = 0.f;
#pragma unroll
        for (int j = 0; j < 5; j++) {
            int idx = q - 2 + j;
            float ww = (idx >= 0 && idx < IN_W) ? tbl[p][j] : 0.f;
            w[p][j] = ww;
            s += ww;
        }
        float inv = 1.0f / s;
#pragma unroll
        for (int j = 0; j < 5; j++) w[p][j] *= inv;
    }
}

__global__ void __launch_bounds__(256)
bicubic4x_sep_kernel(const float* __restrict__ in, float* __restrict__ out)
{
    __shared__ float sin_t[36][40];    // input halo (pad 40 vs 36)
    __shared__ float sh[36][128];      // horizontally-filtered halo rows

    const int tid   = threadIdx.x;
    const int qx0   = blockIdx.x * 32;     // tile origin (input cells)
    const int qy0   = blockIdx.y * 32;
    const int plane = blockIdx.z;

    const float* ip = in + (size_t)plane * PLANE_IN;

    // ---------- Phase A: stage 36x36 halo (clamped) ----------
#pragma unroll
    for (int i = tid; i < 36 * 36; i += 256) {
        int r = i / 36;
        int c = i - r * 36;
        int gy = qy0 - 2 + r;  gy = gy < 0 ? 0 : (gy > IN_H - 1 ? IN_H - 1 : gy);
        int gx = qx0 - 2 + c;  gx = gx < 0 ? 0 : (gx > IN_W - 1 ? IN_W - 1 : gx);
        sin_t[r][c] = __ldg(ip + gy * IN_W + gx);
    }
    __syncthreads();

    // ---------- Phase B: horizontal pass (36 rows x 32 cells) ----------
#pragma unroll
    for (int t = tid; t < 36 * 32; t += 256) {
        int r = t >> 5;           // halo row 0..35
        int q = t & 31;           // local cell 0..31
        int qg = qx0 + q;         // global cell

        float v0 = sin_t[r][q + 0];
        float v1 = sin_t[r][q + 1];
        float v2 = sin_t[r][q + 2];
        float v3 = sin_t[r][q + 3];
        float v4 = sin_t[r][q + 4];

        float4 h;
        if (qg >= 2 && qg <= IN_W - 3) {
            h.x = fmaf(A0, v0, fmaf(A1, v1, fmaf(A2, v2, A3 * v3)));
            h.y = fmaf(B0, v0, fmaf(B1, v1, fmaf(B2, v2, B3 * v3)));
            h.z = fmaf(B3, v1, fmaf(B2, v2, fmaf(B1, v3, B0 * v4)));
            h.w = fmaf(A3, v1, fmaf(A2, v2, fmaf(A1, v3, A0 * v4)));
        } else {
            float wx[4][5];
            border_weights(qg, wx);
            float hv[4];
#pragma unroll
            for (int p = 0; p < 4; p++) {
                float s = wx[p][0] * v0;
                s = fmaf(wx[p][1], v1, s);
                s = fmaf(wx[p][2], v2, s);
                s = fmaf(wx[p][3], v3, s);
                s = fmaf(wx[p][4], v4, s);
                hv[p] = s;
            }
            h = make_float4(hv[0], hv[1], hv[2], hv[3]);
        }
        reinterpret_cast<float4*>(sh[r])[q] = h;
    }
    __syncthreads();

    // ---------- Phase C: vertical pass ----------
    // Thread: cx = tid&31 -> 4 output columns; rg = tid>>5 -> 4 qy cells.
    const int cx = tid & 31;              // float4 column index (ox0 = 4*cx)
    const int rg = tid >> 5;              // 0..7

    float* op_base = out + (size_t)plane * PLANE_OUT + (size_t)(qx0 * 4) + (size_t)cx * 4;

#pragma unroll
    for (int c = 0; c < 4; c++) {
        int qyl = rg * 4 + c;             // local qy cell 0..31
        int qyg = qy0 + qyl;              // global qy cell

        float4 v0 = reinterpret_cast<const float4*>(sh[qyl + 0])[cx];
        float4 v1 = reinterpret_cast<const float4*>(sh[qyl + 1])[cx];
        float4 v2 = reinterpret_cast<const float4*>(sh[qyl + 2])[cx];
        float4 v3 = reinterpret_cast<const float4*>(sh[qyl + 3])[cx];
        float4 v4 = reinterpret_cast<const float4*>(sh[qyl + 4])[cx];

        float4 o[4];
        if (qyg >= 2 && qyg <= IN_H - 3) {
            // phase 0: taps v0..v3 (A), phase 1: v0..v3 (B),
            // phase 2: v1..v4 (B rev), phase 3: v1..v4 (A rev)
            o[0].x = fmaf(A0, v0.x, fmaf(A1, v1.x, fmaf(A2, v2.x, A3 * v3.x)));
            o[0].y = fmaf(A0, v0.y, fmaf(A1, v1.y, fmaf(A2, v2.y, A3 * v3.y)));
            o[0].z = fmaf(A0, v0.z, fmaf(A1, v1.z, fmaf(A2, v2.z, A3 * v3.z)));
            o[0].w = fmaf(A0, v0.w, fmaf(A1, v1.w, fmaf(A2, v2.w, A3 * v3.w)));

            o[1].x = fmaf(B0, v0.x, fmaf(B1, v1.x, fmaf(B2, v2.x, B3 * v3.x)));
            o[1].y = fmaf(B0, v0.y, fmaf(B1, v1.y, fmaf(B2, v2.y, B3 * v3.y)));
            o[1].z = fmaf(B0, v0.z, fmaf(B1, v1.z, fmaf(B2, v2.z, B3 * v3.z)));
            o[1].w = fmaf(B0, v0.w, fmaf(B1, v1.w, fmaf(B2, v2.w, B3 * v3.w)));

            o[2].x = fmaf(B3, v1.x, fmaf(B2, v2.x, fmaf(B1, v3.x, B0 * v4.x)));
            o[2].y = fmaf(B3, v1.y, fmaf(B2, v2.y, fmaf(B1, v3.y, B0 * v4.y)));
            o[2].z = fmaf(B3, v1.z, fmaf(B2, v2.z, fmaf(B1, v3.z, B0 * v4.z)));
            o[2].w = fmaf(B3, v1.w, fmaf(B2, v2.w, fmaf(B1, v3.w, B0 * v4.w)));

            o[3].x = fmaf(A3, v1.x, fmaf(A2, v2.x, fmaf(A1, v3.x, A0 * v4.x)));
            o[3].y = fmaf(A3, v1.y, fmaf(A2, v2.y, fmaf(A1, v3.y, A0 * v4.y)));
            o[3].z = fmaf(A3, v1.z, fmaf(A2, v2.z, fmaf(A1, v3.z, A0 * v4.z)));
            o[3].w = fmaf(A3, v1.w, fmaf(A2, v2.w, fmaf(A1, v3.w, A0 * v4.w)));
        } else {
            float wy[4][5];
            border_weights(qyg, wy);
#pragma unroll
            for (int p = 0; p < 4; p++) {
                float4 s;
                s.x = wy[p][0] * v0.x; s.y = wy[p][0] * v0.y;
                s.z = wy[p][0] * v0.z; s.w = wy[p][0] * v0.w;
                s.x = fmaf(wy[p][1], v1.x, s.x); s.y = fmaf(wy[p][1], v1.y, s.y);
                s.z = fmaf(wy[p][1], v1.z, s.z); s.w = fmaf(wy[p][1], v1.w, s.w);
                s.x = fmaf(wy[p][2], v2.x, s.x); s.y = fmaf(wy[p][2], v2.y, s.y);
                s.z = fmaf(wy[p][2], v2.z, s.z); s.w = fmaf(wy[p][2], v2.w, s.w);
                s.x = fmaf(wy[p][3], v3.x, s.x); s.y = fmaf(wy[p][3], v3.y, s.y);
                s.z = fmaf(wy[p][3], v3.z, s.z); s.w = fmaf(wy[p][3], v3.w, s.w);
                s.x = fmaf(wy[p][4], v4.x, s.x); s.y = fmaf(wy[p][4], v4.y, s.y);
                s.z = fmaf(wy[p][4], v4.z, s.z); s.w = fmaf(wy[p][4], v4.w, s.w);
                o[p] = s;
            }
        }

#pragma unroll
        for (int p = 0; p < 4; p++) {
            int oy = qyg * 4 + p;
            *reinterpret_cast<float4*>(op_base + (size_t)oy * OUT_W) = o[p];
        }
    }
}

extern "C" void kernel_launch(void* const* d_in, const int* in_sizes, int n_in,
                              void* d_out, int out_size)
{
    const float* x   = (const float*)d_in[0];
    float*       out = (float*)d_out;

    dim3 grid(8, 8, 48);   // 8x8 tiles per 256x256 plane, 48 planes
    bicubic4x_sep_kernel<<<grid, 256>>>(x, out);
}